// round 11
// baseline (speedup 1.0000x reference)
#include <cuda_runtime.h>
#include <cuda_fp16.h>
#include <cstdint>

#define N_NODES_MAX 50000
#define N_EDGES_MAX 800000
#define FEAT 128
#define BM 128
#define WPADH 136  // padded half row: 272 B = 17*16B -> conflict-free ldmatrix
#define CAP 64     // per-node bucket capacity (deg ~Poisson(16); overflow handled inline)

// Scratch (allocation-free rule: __device__ globals)
__device__ __half g_h[N_NODES_MAX * FEAT];      // h' = (x@W) * dinv[row], fp16
__device__ int    g_cnt[N_NODES_MAX];           // zero at load; re-zeroed by gather each run
__device__ int    g_list[N_NODES_MAX * CAP];    // bucketed src indices
__device__ int    g_ovf[N_EDGES_MAX];           // overflow edge ids (unused in practice)
__device__ int    g_ovf_cnt;                    // zero at load; reset by last gather block
__device__ int    g_done;                       // gather completion ticket

// ---------------------------------------------------------------------------
// Fill buckets: histogram + bin in one pass
// ---------------------------------------------------------------------------
__global__ void fill_kernel(const int* __restrict__ src, const int* __restrict__ dst,
                            int* cnt, int* list, int* ovf, int* ovf_cnt, int E) {
    int e = blockIdx.x * blockDim.x + threadIdx.x;
    if (e >= E) return;
    int d = __ldg(dst + e);
    int p = atomicAdd(&cnt[d], 1);
    if (p < CAP) list[d * CAP + p] = __ldg(src + e);
    else         ovf[atomicAdd(ovf_cnt, 1)] = e;
}

// ---------------------------------------------------------------------------
// Tensor-core helpers
// ---------------------------------------------------------------------------
__device__ __forceinline__ uint32_t smem_u32(const void* p) {
    return (uint32_t)__cvta_generic_to_shared(p);
}
__device__ __forceinline__ void ldmatrix_x4(uint32_t& r0, uint32_t& r1,
                                            uint32_t& r2, uint32_t& r3, uint32_t addr) {
    asm volatile("ldmatrix.sync.aligned.m8n8.x4.shared.b16 {%0,%1,%2,%3}, [%4];"
                 : "=r"(r0), "=r"(r1), "=r"(r2), "=r"(r3) : "r"(addr));
}
__device__ __forceinline__ void ldmatrix_x2_trans(uint32_t& r0, uint32_t& r1, uint32_t addr) {
    asm volatile("ldmatrix.sync.aligned.m8n8.x2.trans.shared.b16 {%0,%1}, [%2];"
                 : "=r"(r0), "=r"(r1) : "r"(addr));
}
__device__ __forceinline__ void mma16816(float* c, uint32_t a0, uint32_t a1,
                                         uint32_t a2, uint32_t a3,
                                         uint32_t b0, uint32_t b1) {
    asm volatile(
        "mma.sync.aligned.m16n8k16.row.col.f32.f16.f16.f32 "
        "{%0,%1,%2,%3}, {%4,%5,%6,%7}, {%8,%9}, {%0,%1,%2,%3};"
        : "+f"(c[0]), "+f"(c[1]), "+f"(c[2]), "+f"(c[3])
        : "r"(a0), "r"(a1), "r"(a2), "r"(a3), "r"(b0), "r"(b1));
}

// ---------------------------------------------------------------------------
// GEMM: h' = (x @ W) * rsqrt(cnt[row]+1), fp16 out. Tile 128x128, 512 threads.
// W converted fp32->fp16 during smem staging (no separate prep pass).
// ---------------------------------------------------------------------------
__global__ void __launch_bounds__(512)
gemm_kernel(const float* __restrict__ x, const float* __restrict__ W,
            const int* __restrict__ cnt, __half* __restrict__ h, int n) {
    extern __shared__ __half sh[];
    __half* Wh = sh;                    // [128][WPADH]
    __half* Xh = sh + FEAT * WPADH;     // [BM][WPADH]

    int tid = threadIdx.x;
    int r0blk = blockIdx.x * BM;

    // Stage W (fp32 -> fp16): 128x32 float4 = 4096
    {
        const float4* w4 = reinterpret_cast<const float4*>(W);
#pragma unroll
        for (int i = 0; i < 8; i++) {
            int idx = i * 512 + tid;
            int r = idx >> 5, c4 = idx & 31;
            float4 v = w4[idx];
            __half2* d = reinterpret_cast<__half2*>(Wh + r * WPADH + c4 * 4);
            d[0] = __floats2half2_rn(v.x, v.y);
            d[1] = __floats2half2_rn(v.z, v.w);
        }
    }
    // Stage X tile (fp32 -> fp16): 128x32 float4 = 4096
    {
        const float4* x4 = reinterpret_cast<const float4*>(x);
#pragma unroll
        for (int i = 0; i < 8; i++) {
            int idx = i * 512 + tid;
            int r = idx >> 5, c4 = idx & 31;
            int row = r0blk + r;
            float4 v = make_float4(0.f, 0.f, 0.f, 0.f);
            if (row < n) v = x4[(size_t)row * 32 + c4];
            __half2* d = reinterpret_cast<__half2*>(Xh + r * WPADH + c4 * 4);
            d[0] = __floats2half2_rn(v.x, v.y);
            d[1] = __floats2half2_rn(v.z, v.w);
        }
    }
    __syncthreads();

    int w = tid >> 5, lane = tid & 31;
    int wr = w & 7;        // 8 row groups of 16
    int wc = w >> 3;       // 2 col groups of 64

    float acc[8][4];
#pragma unroll
    for (int nt = 0; nt < 8; nt++)
#pragma unroll
        for (int j = 0; j < 4; j++) acc[nt][j] = 0.f;

    int t = lane >> 3, r8 = lane & 7;
    int a_row = wr * 16 + (t & 1) * 8 + r8;
    int a_kof = (t >> 1) * 8;
    uint32_t a_base = smem_u32(Xh + a_row * WPADH + a_kof);
    int bt = (lane >> 3) & 1;
    uint32_t b_base = smem_u32(Wh + (bt * 8 + r8) * WPADH + wc * 64);

#pragma unroll
    for (int kk = 0; kk < 8; kk++) {
        uint32_t a0, a1, a2, a3;
        ldmatrix_x4(a0, a1, a2, a3, a_base + kk * 16 * sizeof(__half));
        uint32_t brow = b_base + kk * 16 * WPADH * sizeof(__half);
#pragma unroll
        for (int nt = 0; nt < 8; nt++) {
            uint32_t b0, b1;
            ldmatrix_x2_trans(b0, b1, brow + nt * 8 * sizeof(__half));
            mma16816(acc[nt], a0, a1, a2, a3, b0, b1);
        }
    }

    int group = lane >> 2, tg = lane & 3;
    int r_lo = r0blk + wr * 16 + group;
    int r_hi = r_lo + 8;
    float di_lo = (r_lo < n) ? rsqrtf((float)(__ldg(cnt + r_lo) + 1)) : 0.f;
    float di_hi = (r_hi < n) ? rsqrtf((float)(__ldg(cnt + r_hi) + 1)) : 0.f;

#pragma unroll
    for (int nt = 0; nt < 8; nt++) {
        int col = wc * 64 + nt * 8 + tg * 2;
        if (r_lo < n)
            *reinterpret_cast<__half2*>(h + (size_t)r_lo * FEAT + col) =
                __floats2half2_rn(acc[nt][0] * di_lo, acc[nt][1] * di_lo);
        if (r_hi < n)
            *reinterpret_cast<__half2*>(h + (size_t)r_hi * FEAT + col) =
                __floats2half2_rn(acc[nt][2] * di_hi, acc[nt][3] * di_hi);
    }
}

// ---------------------------------------------------------------------------
// Gather: warp per node, split into 2 half-warps of 16 lanes.
// Each lane loads a uint4 (8 halves) so 16 lanes cover one 256B row;
// half 0 takes even edges, half 1 odd. Halves combined via shfl_xor(16).
// result = gelu(dd * (h'[node] + sum h'[s]) + b), one float4 store per lane.
// ---------------------------------------------------------------------------
__device__ __forceinline__ float gelu_fast(float v) {
    // 0.5*v*(1+tanh(0.7978845608*(v + 0.044715*v^3)))
    float t = fmaf(0.044715f * v, v * v, v) * 0.7978845608f;
    float th;
    asm("tanh.approx.f32 %0, %1;" : "=f"(th) : "f"(t));
    return 0.5f * v * (1.0f + th);
}

__device__ __forceinline__ void add_row_f32(float* acc, uint4 hv) {
    const __half2* p = reinterpret_cast<const __half2*>(&hv);
#pragma unroll
    for (int q = 0; q < 4; q++) {
        float2 f = __half22float2(p[q]);
        acc[2 * q] += f.x;
        acc[2 * q + 1] += f.y;
    }
}

__global__ void __launch_bounds__(256)
gather_kernel(int* __restrict__ cnt, const int* __restrict__ list,
              const __half* __restrict__ h,
              const int* __restrict__ src, const int* __restrict__ dst,
              const int* __restrict__ ovf, int* __restrict__ ovf_cnt,
              int* __restrict__ done,
              const float* __restrict__ b, float* out, int n) {
    int node = blockIdx.x * 8 + (threadIdx.x >> 5);
    int lane = threadIdx.x & 31;

    if (node < n) {
        int half = lane >> 4;   // 0: even edges, 1: odd edges
        int lg   = lane & 15;   // feature chunk: halves [lg*8, lg*8+8)
        const uint4* hb = reinterpret_cast<const uint4*>(h);

        int m = cnt[node];
        float dd = rsqrtf((float)(m + 1));

        float acc[8];
#pragma unroll
        for (int i = 0; i < 8; i++) acc[i] = 0.f;

        // self loop (half 0 only; halves are summed at the end)
        if (half == 0) add_row_f32(acc, hb[(size_t)node * 16 + lg]);

        int mb = (m > CAP) ? CAP : m;
        const int* lp = list + (size_t)node * CAP;

        for (int base = 0; base < mb; base += 32) {
            int idx = base + lane;
            int s = (idx < mb) ? lp[idx] : 0;
            int cnum = mb - base; if (cnum > 32) cnum = 32;
            int j = 0;
            // 8 edges per iter: this lane handles 4 (its parity)
            for (; j + 7 < cnum; j += 8) {
                uint4 hv[4];
#pragma unroll
                for (int q = 0; q < 4; q++) {
                    int sq = __shfl_sync(0xFFFFFFFFu, s, j + 2 * q + half);
                    hv[q] = hb[(size_t)sq * 16 + lg];
                }
                // 2-level fp16 tree per half2 position, then one fp32 add
#pragma unroll
                for (int p = 0; p < 4; p++) {
                    __half2 a0 = reinterpret_cast<const __half2*>(&hv[0])[p];
                    __half2 a1 = reinterpret_cast<const __half2*>(&hv[1])[p];
                    __half2 a2 = reinterpret_cast<const __half2*>(&hv[2])[p];
                    __half2 a3 = reinterpret_cast<const __half2*>(&hv[3])[p];
                    __half2 tsum = __hadd2(__hadd2(a0, a1), __hadd2(a2, a3));
                    float2 f = __half22float2(tsum);
                    acc[2 * p] += f.x;
                    acc[2 * p + 1] += f.y;
                }
            }
            // tail pairs (exact fp32 path)
            for (; j < cnum; j += 2) {
                int jj = j + half;
                int sq = __shfl_sync(0xFFFFFFFFu, s, (jj < 32) ? jj : 0);
                if (jj < cnum) add_row_f32(acc, hb[(size_t)sq * 16 + lg]);
            }
        }

        if (m > CAP) {  // inline overflow scan (empty in practice); half 0 only
            int movf = *ovf_cnt;
            for (int i = 0; i < movf; i++) {
                int e = __ldg(ovf + i);
                if (__ldg(dst + e) == node && half == 0)
                    add_row_f32(acc, hb[(size_t)__ldg(src + e) * 16 + lg]);
            }
        }

        // combine the two halves
#pragma unroll
        for (int i = 0; i < 8; i++)
            acc[i] += __shfl_xor_sync(0xFFFFFFFFu, acc[i], 16);

        // each lane finishes + stores only its float4 (half selects low/high 4)
        float a0 = half ? acc[4] : acc[0];
        float a1 = half ? acc[5] : acc[1];
        float a2 = half ? acc[6] : acc[2];
        float a3 = half ? acc[7] : acc[3];
        float4 bb = reinterpret_cast<const float4*>(b)[2 * lg + half];
        float4 r;
        r.x = gelu_fast(fmaf(dd, a0, bb.x));
        r.y = gelu_fast(fmaf(dd, a1, bb.y));
        r.z = gelu_fast(fmaf(dd, a2, bb.z));
        r.w = gelu_fast(fmaf(dd, a3, bb.w));
        reinterpret_cast<float4*>(out + (size_t)node * FEAT)[2 * lg + half] = r;

        // reset cnt for next replay (zero at load; restored every run)
        if (lane == 0) cnt[node] = 0;
    }

    // last block to finish resets overflow state (ordered after all reads)
    __syncthreads();
    if (threadIdx.x == 0) {
        int t = atomicAdd(done, 1);
        if (t == (int)gridDim.x - 1) {
            *done = 0;
            *ovf_cnt = 0;
        }
    }
}

// ---------------------------------------------------------------------------
// Launch: 3 kernels total (fill -> gemm -> gather)
// ---------------------------------------------------------------------------
extern "C" void kernel_launch(void* const* d_in, const int* in_sizes, int n_in,
                              void* d_out, int out_size) {
    const float* x  = (const float*)d_in[0];
    const int*   ei = (const int*)d_in[1];
    const float* W  = (const float*)d_in[2];
    const float* b  = (const float*)d_in[3];
    float* out = (float*)d_out;

    int n = in_sizes[0] / FEAT;
    int E = in_sizes[1] / 2;
    const int* src = ei;
    const int* dst = ei + E;

    __half* h_ptr;
    int *cnt_ptr, *list_ptr, *ovf_ptr, *ovfc_ptr, *done_ptr;
    cudaGetSymbolAddress((void**)&h_ptr, g_h);
    cudaGetSymbolAddress((void**)&cnt_ptr, g_cnt);
    cudaGetSymbolAddress((void**)&list_ptr, g_list);
    cudaGetSymbolAddress((void**)&ovf_ptr, g_ovf);
    cudaGetSymbolAddress((void**)&ovfc_ptr, g_ovf_cnt);
    cudaGetSymbolAddress((void**)&done_ptr, g_done);

    fill_kernel<<<(E + 255) / 256, 256>>>(src, dst, cnt_ptr, list_ptr, ovf_ptr, ovfc_ptr, E);

    int smem_bytes = (FEAT + BM) * WPADH * (int)sizeof(__half);  // ~68 KB
    cudaFuncSetAttribute(gemm_kernel, cudaFuncAttributeMaxDynamicSharedMemorySize, smem_bytes);
    gemm_kernel<<<(n + BM - 1) / BM, 512, smem_bytes>>>(x, W, cnt_ptr, h_ptr, n);

    gather_kernel<<<(n + 7) / 8, 256>>>(cnt_ptr, list_ptr, h_ptr,
                                        src, dst, ovf_ptr, ovfc_ptr, done_ptr,
                                        b, out, n);
}

// round 12
// speedup vs baseline: 1.0255x; 1.0255x over previous
#include <cuda_runtime.h>
#include <cuda_fp16.h>
#include <cstdint>

#define N_NODES_MAX 50000
#define N_EDGES_MAX 800000
#define FEAT 128
#define BM 128
#define WPADH 136  // padded half row: 272 B = 17*16B -> conflict-free ldmatrix
#define CAP 64     // per-node bucket capacity (deg ~Poisson(16); overflow handled inline)

// Scratch (allocation-free rule: __device__ globals)
__device__ __half g_h[N_NODES_MAX * FEAT];      // h' = (x@W) * dinv[row], fp16
__device__ __half g_wh[FEAT * FEAT];            // fp16 W (converted once per launch)
__device__ int    g_cnt[N_NODES_MAX];           // zero at load; re-zeroed by gather each run
__device__ int    g_list[N_NODES_MAX * CAP];    // bucketed src indices
__device__ int    g_ovf[N_EDGES_MAX];           // overflow edge ids (unused in practice)
__device__ int    g_ovf_cnt;

// ---------------------------------------------------------------------------
// Prep: convert W to fp16 + reset overflow counter
// ---------------------------------------------------------------------------
__global__ void prep_kernel(const float* __restrict__ W, __half* __restrict__ wh,
                            int* ovf_cnt) {
    int i = blockIdx.x * blockDim.x + threadIdx.x;
    if (i == 0) *ovf_cnt = 0;
    if (i < FEAT * FEAT / 4) {
        float4 v = reinterpret_cast<const float4*>(W)[i];
        __half2* d = reinterpret_cast<__half2*>(wh + i * 4);
        d[0] = __floats2half2_rn(v.x, v.y);
        d[1] = __floats2half2_rn(v.z, v.w);
    }
}

// ---------------------------------------------------------------------------
// Fill buckets: 4 edges per thread, int4-vectorized index loads, 4 independent
// atomics in flight (MLP=4 against the ~318cyc ATOMG latency).
// ---------------------------------------------------------------------------
__global__ void fill_kernel(const int* __restrict__ src, const int* __restrict__ dst,
                            int* cnt, int* list, int* ovf, int* ovf_cnt, int E) {
    int i = blockIdx.x * blockDim.x + threadIdx.x;
    int base = i * 4;
    if (base + 3 < E) {
        int4 d4 = *reinterpret_cast<const int4*>(dst + base);
        int4 s4 = *reinterpret_cast<const int4*>(src + base);
        int p0 = atomicAdd(&cnt[d4.x], 1);
        int p1 = atomicAdd(&cnt[d4.y], 1);
        int p2 = atomicAdd(&cnt[d4.z], 1);
        int p3 = atomicAdd(&cnt[d4.w], 1);
        if (p0 < CAP) list[d4.x * CAP + p0] = s4.x; else ovf[atomicAdd(ovf_cnt, 1)] = base;
        if (p1 < CAP) list[d4.y * CAP + p1] = s4.y; else ovf[atomicAdd(ovf_cnt, 1)] = base + 1;
        if (p2 < CAP) list[d4.z * CAP + p2] = s4.z; else ovf[atomicAdd(ovf_cnt, 1)] = base + 2;
        if (p3 < CAP) list[d4.w * CAP + p3] = s4.w; else ovf[atomicAdd(ovf_cnt, 1)] = base + 3;
    } else {
        for (int e = base; e < E; e++) {
            int d = __ldg(dst + e);
            int p = atomicAdd(&cnt[d], 1);
            if (p < CAP) list[d * CAP + p] = __ldg(src + e);
            else         ovf[atomicAdd(ovf_cnt, 1)] = e;
        }
    }
}

// ---------------------------------------------------------------------------
// Tensor-core helpers
// ---------------------------------------------------------------------------
__device__ __forceinline__ uint32_t smem_u32(const void* p) {
    return (uint32_t)__cvta_generic_to_shared(p);
}
__device__ __forceinline__ void ldmatrix_x4(uint32_t& r0, uint32_t& r1,
                                            uint32_t& r2, uint32_t& r3, uint32_t addr) {
    asm volatile("ldmatrix.sync.aligned.m8n8.x4.shared.b16 {%0,%1,%2,%3}, [%4];"
                 : "=r"(r0), "=r"(r1), "=r"(r2), "=r"(r3) : "r"(addr));
}
__device__ __forceinline__ void ldmatrix_x2_trans(uint32_t& r0, uint32_t& r1, uint32_t addr) {
    asm volatile("ldmatrix.sync.aligned.m8n8.x2.trans.shared.b16 {%0,%1}, [%2];"
                 : "=r"(r0), "=r"(r1) : "r"(addr));
}
__device__ __forceinline__ void mma16816(float* c, uint32_t a0, uint32_t a1,
                                         uint32_t a2, uint32_t a3,
                                         uint32_t b0, uint32_t b1) {
    asm volatile(
        "mma.sync.aligned.m16n8k16.row.col.f32.f16.f16.f32 "
        "{%0,%1,%2,%3}, {%4,%5,%6,%7}, {%8,%9}, {%0,%1,%2,%3};"
        : "+f"(c[0]), "+f"(c[1]), "+f"(c[2]), "+f"(c[3])
        : "r"(a0), "r"(a1), "r"(a2), "r"(a3), "r"(b0), "r"(b1));
}

// ---------------------------------------------------------------------------
// GEMM: h' = (x @ W) * rsqrt(cnt[row]+1), fp16 out. Tile 128x128, 512 threads.
// ---------------------------------------------------------------------------
__global__ void __launch_bounds__(512)
gemm_kernel(const float* __restrict__ x, const __half* __restrict__ wh,
            const int* __restrict__ cnt, __half* __restrict__ h, int n) {
    extern __shared__ __half sh[];
    __half* Wh = sh;                    // [128][WPADH]
    __half* Xh = sh + FEAT * WPADH;     // [BM][WPADH]

    int tid = threadIdx.x;
    int r0blk = blockIdx.x * BM;

    // Stage W (already fp16): 2048 uint4
    {
        const uint4* w4 = reinterpret_cast<const uint4*>(wh);
#pragma unroll
        for (int i = 0; i < 4; i++) {
            int idx = i * 512 + tid;
            int r = idx >> 4, c = idx & 15;
            *reinterpret_cast<uint4*>(Wh + r * WPADH + c * 8) = w4[idx];
        }
    }
    // Stage X tile (fp32 -> fp16): 128x32 float4 = 4096
    {
        const float4* x4 = reinterpret_cast<const float4*>(x);
#pragma unroll
        for (int i = 0; i < 8; i++) {
            int idx = i * 512 + tid;
            int r = idx >> 5, c4 = idx & 31;
            int row = r0blk + r;
            float4 v = make_float4(0.f, 0.f, 0.f, 0.f);
            if (row < n) v = x4[(size_t)row * 32 + c4];
            __half2* d = reinterpret_cast<__half2*>(Xh + r * WPADH + c4 * 4);
            d[0] = __floats2half2_rn(v.x, v.y);
            d[1] = __floats2half2_rn(v.z, v.w);
        }
    }
    __syncthreads();

    int w = tid >> 5, lane = tid & 31;
    int wr = w & 7;        // 8 row groups of 16
    int wc = w >> 3;       // 2 col groups of 64

    float acc[8][4];
#pragma unroll
    for (int nt = 0; nt < 8; nt++)
#pragma unroll
        for (int j = 0; j < 4; j++) acc[nt][j] = 0.f;

    int t = lane >> 3, r8 = lane & 7;
    int a_row = wr * 16 + (t & 1) * 8 + r8;
    int a_kof = (t >> 1) * 8;
    uint32_t a_base = smem_u32(Xh + a_row * WPADH + a_kof);
    int bt = (lane >> 3) & 1;
    uint32_t b_base = smem_u32(Wh + (bt * 8 + r8) * WPADH + wc * 64);

#pragma unroll
    for (int kk = 0; kk < 8; kk++) {
        uint32_t a0, a1, a2, a3;
        ldmatrix_x4(a0, a1, a2, a3, a_base + kk * 16 * sizeof(__half));
        uint32_t brow = b_base + kk * 16 * WPADH * sizeof(__half);
#pragma unroll
        for (int nt = 0; nt < 8; nt++) {
            uint32_t b0, b1;
            ldmatrix_x2_trans(b0, b1, brow + nt * 8 * sizeof(__half));
            mma16816(acc[nt], a0, a1, a2, a3, b0, b1);
        }
    }

    int group = lane >> 2, tg = lane & 3;
    int r_lo = r0blk + wr * 16 + group;
    int r_hi = r_lo + 8;
    float di_lo = (r_lo < n) ? rsqrtf((float)(__ldg(cnt + r_lo) + 1)) : 0.f;
    float di_hi = (r_hi < n) ? rsqrtf((float)(__ldg(cnt + r_hi) + 1)) : 0.f;

#pragma unroll
    for (int nt = 0; nt < 8; nt++) {
        int col = wc * 64 + nt * 8 + tg * 2;
        if (r_lo < n)
            *reinterpret_cast<__half2*>(h + (size_t)r_lo * FEAT + col) =
                __floats2half2_rn(acc[nt][0] * di_lo, acc[nt][1] * di_lo);
        if (r_hi < n)
            *reinterpret_cast<__half2*>(h + (size_t)r_hi * FEAT + col) =
                __floats2half2_rn(acc[nt][2] * di_hi, acc[nt][3] * di_hi);
    }
}

// ---------------------------------------------------------------------------
// Gather: warp per node. result = gelu(dd * (h'[node] + sum h'[s]) + b).
// GELU via hardware tanh.approx (MUFU.TANH); 8-edge unroll with 2-level fp16
// HADD2 tree; exact fp32 tail + self-loop. (Round-10 proven configuration.)
// ---------------------------------------------------------------------------
__device__ __forceinline__ float gelu_fast(float v) {
    // 0.5*v*(1+tanh(0.7978845608*(v + 0.044715*v^3)))
    float t = fmaf(0.044715f * v, v * v, v) * 0.7978845608f;
    float th;
    asm("tanh.approx.f32 %0, %1;" : "=f"(th) : "f"(t));
    return 0.5f * v * (1.0f + th);
}

__device__ __forceinline__ void acc_row(float4& acc, const uint2* __restrict__ hb, int s) {
    uint2 hv = hb[s * 32];
    float2 fa = __half22float2(*reinterpret_cast<const __half2*>(&hv.x));
    float2 fb = __half22float2(*reinterpret_cast<const __half2*>(&hv.y));
    acc.x += fa.x; acc.y += fa.y; acc.z += fb.x; acc.w += fb.y;
}

__device__ __forceinline__ void acc_quad(float4& acc, const uint2 hv[4]) {
    const __half2* p0 = reinterpret_cast<const __half2*>(&hv[0]);
    const __half2* p1 = reinterpret_cast<const __half2*>(&hv[1]);
    const __half2* p2 = reinterpret_cast<const __half2*>(&hv[2]);
    const __half2* p3 = reinterpret_cast<const __half2*>(&hv[3]);
    __half2 xs = __hadd2(__hadd2(p0[0], p1[0]), __hadd2(p2[0], p3[0]));
    __half2 ys = __hadd2(__hadd2(p0[1], p1[1]), __hadd2(p2[1], p3[1]));
    float2 fx = __half22float2(xs);
    float2 fy = __half22float2(ys);
    acc.x += fx.x; acc.y += fx.y; acc.z += fy.x; acc.w += fy.y;
}

__global__ void __launch_bounds__(256)
gather_kernel(int* __restrict__ cnt, const int* __restrict__ list,
              const __half* __restrict__ h,
              const int* __restrict__ src, const int* __restrict__ dst,
              const int* __restrict__ ovf, const int* __restrict__ ovf_cnt,
              const float* __restrict__ b, float* out, int n) {
    int node = blockIdx.x * 8 + (threadIdx.x >> 5);
    if (node >= n) return;
    int lane = threadIdx.x & 31;

    int m = cnt[node];
    float dd = rsqrtf((float)(m + 1));

    const uint2* hb = reinterpret_cast<const uint2*>(h) + lane;  // row stride = 32 uint2

    float4 acc = make_float4(0.f, 0.f, 0.f, 0.f);
    acc_row(acc, hb, node);  // self loop: h'[node], exact fp32 path

    int mb = (m > CAP) ? CAP : m;
    const int* lp = list + (size_t)node * CAP;

    for (int base = 0; base < mb; base += 32) {
        int idx = base + lane;
        int s = (idx < mb) ? lp[idx] : 0;
        int cnum = mb - base; if (cnum > 32) cnum = 32;
        int j = 0;
        for (; j + 7 < cnum; j += 8) {
            uint2 hv[8];
#pragma unroll
            for (int q = 0; q < 8; q++) {
                int sq = __shfl_sync(0xFFFFFFFFu, s, j + q);
                hv[q] = hb[sq * 32];
            }
            acc_quad(acc, hv);
            acc_quad(acc, hv + 4);
        }
        for (; j < cnum; j++) {
            int sj = __shfl_sync(0xFFFFFFFFu, s, j);
            acc_row(acc, hb, sj);  // exact fp32 tail
        }
    }

    if (m > CAP) {  // inline overflow scan (ovf list empty in practice)
        int movf = *ovf_cnt;
        for (int i = 0; i < movf; i++) {
            int e = __ldg(ovf + i);
            if (__ldg(dst + e) == node) acc_row(acc, hb, __ldg(src + e));
        }
    }

    float4 bb = *(reinterpret_cast<const float4*>(b) + lane);
    acc.x = gelu_fast(fmaf(dd, acc.x, bb.x));
    acc.y = gelu_fast(fmaf(dd, acc.y, bb.y));
    acc.z = gelu_fast(fmaf(dd, acc.z, bb.z));
    acc.w = gelu_fast(fmaf(dd, acc.w, bb.w));
    *(reinterpret_cast<float4*>(out + (size_t)node * FEAT) + lane) = acc;

    // Reset cnt for the next replay (zero at module load; restored every run).
    if (lane == 0) cnt[node] = 0;
}

// ---------------------------------------------------------------------------
// Launch: 4 kernels total (prep -> fill -> gemm -> gather)
// ---------------------------------------------------------------------------
extern "C" void kernel_launch(void* const* d_in, const int* in_sizes, int n_in,
                              void* d_out, int out_size) {
    const float* x  = (const float*)d_in[0];
    const int*   ei = (const int*)d_in[1];
    const float* W  = (const float*)d_in[2];
    const float* b  = (const float*)d_in[3];
    float* out = (float*)d_out;

    int n = in_sizes[0] / FEAT;
    int E = in_sizes[1] / 2;
    const int* src = ei;
    const int* dst = ei + E;

    __half *h_ptr, *wh_ptr;
    int *cnt_ptr, *list_ptr, *ovf_ptr, *ovfc_ptr;
    cudaGetSymbolAddress((void**)&h_ptr, g_h);
    cudaGetSymbolAddress((void**)&wh_ptr, g_wh);
    cudaGetSymbolAddress((void**)&cnt_ptr, g_cnt);
    cudaGetSymbolAddress((void**)&list_ptr, g_list);
    cudaGetSymbolAddress((void**)&ovf_ptr, g_ovf);
    cudaGetSymbolAddress((void**)&ovfc_ptr, g_ovf_cnt);

    prep_kernel<<<(FEAT * FEAT / 4 + 255) / 256, 256>>>(W, wh_ptr, ovfc_ptr);

    int fill_threads = (E + 3) / 4;
    fill_kernel<<<(fill_threads + 255) / 256, 256>>>(src, dst, cnt_ptr, list_ptr,
                                                     ovf_ptr, ovfc_ptr, E);

    int smem_bytes = (FEAT + BM) * WPADH * (int)sizeof(__half);  // ~68 KB
    cudaFuncSetAttribute(gemm_kernel, cudaFuncAttributeMaxDynamicSharedMemorySize, smem_bytes);
    gemm_kernel<<<(n + BM - 1) / BM, 512, smem_bytes>>>(x, wh_ptr, cnt_ptr, h_ptr, n);

    gather_kernel<<<(n + 7) / 8, 256>>>(cnt_ptr, list_ptr, h_ptr,
                                        src, dst, ovf_ptr, ovfc_ptr, b, out, n);
}

// round 14
// speedup vs baseline: 1.0838x; 1.0569x over previous
#include <cuda_runtime.h>
#include <cuda_fp16.h>
#include <cstdint>

#define N_NODES_MAX 50000
#define N_EDGES_MAX 800000
#define FEAT 128
#define BM 128
#define WPADH 136  // padded half row: 272 B = 17*16B -> conflict-free ldmatrix
#define CAP 64     // per-node bucket capacity (deg ~Poisson(16); overflow handled inline)

// Scratch (allocation-free rule: __device__ globals)
__device__ __half g_h[N_NODES_MAX * FEAT];      // h' = (x@W) * dinv[row], fp16
__device__ __half g_wh[FEAT * FEAT];            // fp16 W (converted once per launch)
__device__ int    g_cnt[N_NODES_MAX];           // zero at load; re-zeroed by gather each run
__device__ int    g_list[N_NODES_MAX * CAP];    // bucketed src indices
__device__ int    g_ovf[N_EDGES_MAX];           // overflow edge ids (unused in practice)
__device__ int    g_ovf_cnt;

// ---------------------------------------------------------------------------
// Prep: convert W to fp16 + reset overflow counter
// ---------------------------------------------------------------------------
__global__ void prep_kernel(const float* __restrict__ W, __half* __restrict__ wh,
                            int* ovf_cnt) {
    int i = blockIdx.x * blockDim.x + threadIdx.x;
    if (i == 0) *ovf_cnt = 0;
    if (i < FEAT * FEAT / 4) {
        float4 v = reinterpret_cast<const float4*>(W)[i];
        __half2* d = reinterpret_cast<__half2*>(wh + i * 4);
        d[0] = __floats2half2_rn(v.x, v.y);
        d[1] = __floats2half2_rn(v.z, v.w);
    }
}

// ---------------------------------------------------------------------------
// Fill buckets: 4 edges/thread (782 blocks = single wave). Releases the
// dependent gemm launch immediately via griddepcontrol.launch_dependents —
// gemm's MMA mainloop overlaps fill; gemm waits before reading cnt.
// ---------------------------------------------------------------------------
__global__ void __launch_bounds__(256)
fill_kernel(const int* __restrict__ src, const int* __restrict__ dst,
            int* cnt, int* list, int* ovf, int* ovf_cnt, int E) {
    asm volatile("griddepcontrol.launch_dependents;");
    int i = blockIdx.x * blockDim.x + threadIdx.x;
    int base = i * 4;
    if (base + 3 < E) {
        int4 d4 = *reinterpret_cast<const int4*>(dst + base);
        int4 s4 = *reinterpret_cast<const int4*>(src + base);
        int p0 = atomicAdd(&cnt[d4.x], 1);
        int p1 = atomicAdd(&cnt[d4.y], 1);
        int p2 = atomicAdd(&cnt[d4.z], 1);
        int p3 = atomicAdd(&cnt[d4.w], 1);
        if (p0 < CAP) list[d4.x * CAP + p0] = s4.x; else ovf[atomicAdd(ovf_cnt, 1)] = base;
        if (p1 < CAP) list[d4.y * CAP + p1] = s4.y; else ovf[atomicAdd(ovf_cnt, 1)] = base + 1;
        if (p2 < CAP) list[d4.z * CAP + p2] = s4.z; else ovf[atomicAdd(ovf_cnt, 1)] = base + 2;
        if (p3 < CAP) list[d4.w * CAP + p3] = s4.w; else ovf[atomicAdd(ovf_cnt, 1)] = base + 3;
    } else {
        for (int e = base; e < E; e++) {
            int d = __ldg(dst + e);
            int p = atomicAdd(&cnt[d], 1);
            if (p < CAP) list[d * CAP + p] = __ldg(src + e);
            else         ovf[atomicAdd(ovf_cnt, 1)] = e;
        }
    }
}

// ---------------------------------------------------------------------------
// Tensor-core helpers
// ---------------------------------------------------------------------------
__device__ __forceinline__ uint32_t smem_u32(const void* p) {
    return (uint32_t)__cvta_generic_to_shared(p);
}
__device__ __forceinline__ void ldmatrix_x4(uint32_t& r0, uint32_t& r1,
                                            uint32_t& r2, uint32_t& r3, uint32_t addr) {
    asm volatile("ldmatrix.sync.aligned.m8n8.x4.shared.b16 {%0,%1,%2,%3}, [%4];"
                 : "=r"(r0), "=r"(r1), "=r"(r2), "=r"(r3) : "r"(addr));
}
__device__ __forceinline__ void ldmatrix_x2_trans(uint32_t& r0, uint32_t& r1, uint32_t addr) {
    asm volatile("ldmatrix.sync.aligned.m8n8.x2.trans.shared.b16 {%0,%1}, [%2];"
                 : "=r"(r0), "=r"(r1) : "r"(addr));
}
__device__ __forceinline__ void mma16816(float* c, uint32_t a0, uint32_t a1,
                                         uint32_t a2, uint32_t a3,
                                         uint32_t b0, uint32_t b1) {
    asm volatile(
        "mma.sync.aligned.m16n8k16.row.col.f32.f16.f16.f32 "
        "{%0,%1,%2,%3}, {%4,%5,%6,%7}, {%8,%9}, {%0,%1,%2,%3};"
        : "+f"(c[0]), "+f"(c[1]), "+f"(c[2]), "+f"(c[3])
        : "r"(a0), "r"(a1), "r"(a2), "r"(a3), "r"(b0), "r"(b1));
}

// ---------------------------------------------------------------------------
// GEMM: h' = (x @ W) * rsqrt(cnt[row]+1), fp16 out. Tile 128x128, 512 threads.
// Launched with programmatic stream serialization: the stage + MMA mainloop
// overlaps fill; griddepcontrol.wait before the cnt-dependent epilogue.
// ---------------------------------------------------------------------------
__global__ void __launch_bounds__(512)
gemm_kernel(const float* __restrict__ x, const __half* __restrict__ wh,
            const int* __restrict__ cnt, __half* __restrict__ h, int n) {
    extern __shared__ __half sh[];
    __half* Wh = sh;                    // [128][WPADH]
    __half* Xh = sh + FEAT * WPADH;     // [BM][WPADH]

    int tid = threadIdx.x;
    int r0blk = blockIdx.x * BM;

    // Stage W (already fp16): 2048 uint4
    {
        const uint4* w4 = reinterpret_cast<const uint4*>(wh);
#pragma unroll
        for (int i = 0; i < 4; i++) {
            int idx = i * 512 + tid;
            int r = idx >> 4, c = idx & 15;
            *reinterpret_cast<uint4*>(Wh + r * WPADH + c * 8) = w4[idx];
        }
    }
    // Stage X tile (fp32 -> fp16): 128x32 float4 = 4096
    {
        const float4* x4 = reinterpret_cast<const float4*>(x);
#pragma unroll
        for (int i = 0; i < 8; i++) {
            int idx = i * 512 + tid;
            int r = idx >> 5, c4 = idx & 31;
            int row = r0blk + r;
            float4 v = make_float4(0.f, 0.f, 0.f, 0.f);
            if (row < n) v = x4[(size_t)row * 32 + c4];
            __half2* d = reinterpret_cast<__half2*>(Xh + r * WPADH + c4 * 4);
            d[0] = __floats2half2_rn(v.x, v.y);
            d[1] = __floats2half2_rn(v.z, v.w);
        }
    }
    __syncthreads();

    int w = tid >> 5, lane = tid & 31;
    int wr = w & 7;        // 8 row groups of 16
    int wc = w >> 3;       // 2 col groups of 64

    float acc[8][4];
#pragma unroll
    for (int nt = 0; nt < 8; nt++)
#pragma unroll
        for (int j = 0; j < 4; j++) acc[nt][j] = 0.f;

    int t = lane >> 3, r8 = lane & 7;
    int a_row = wr * 16 + (t & 1) * 8 + r8;
    int a_kof = (t >> 1) * 8;
    uint32_t a_base = smem_u32(Xh + a_row * WPADH + a_kof);
    int bt = (lane >> 3) & 1;
    uint32_t b_base = smem_u32(Wh + (bt * 8 + r8) * WPADH + wc * 64);

#pragma unroll
    for (int kk = 0; kk < 8; kk++) {
        uint32_t a0, a1, a2, a3;
        ldmatrix_x4(a0, a1, a2, a3, a_base + kk * 16 * sizeof(__half));
        uint32_t brow = b_base + kk * 16 * WPADH * sizeof(__half);
#pragma unroll
        for (int nt = 0; nt < 8; nt++) {
            uint32_t b0, b1;
            ldmatrix_x2_trans(b0, b1, brow + nt * 8 * sizeof(__half));
            mma16816(acc[nt], a0, a1, a2, a3, b0, b1);
        }
    }

    // Wait for fill (primary) to complete before consuming cnt.
    asm volatile("griddepcontrol.wait;" ::: "memory");

    int group = lane >> 2, tg = lane & 3;
    int r_lo = r0blk + wr * 16 + group;
    int r_hi = r_lo + 8;
    float di_lo = (r_lo < n) ? rsqrtf((float)(__ldg(cnt + r_lo) + 1)) : 0.f;
    float di_hi = (r_hi < n) ? rsqrtf((float)(__ldg(cnt + r_hi) + 1)) : 0.f;

#pragma unroll
    for (int nt = 0; nt < 8; nt++) {
        int col = wc * 64 + nt * 8 + tg * 2;
        if (r_lo < n)
            *reinterpret_cast<__half2*>(h + (size_t)r_lo * FEAT + col) =
                __floats2half2_rn(acc[nt][0] * di_lo, acc[nt][1] * di_lo);
        if (r_hi < n)
            *reinterpret_cast<__half2*>(h + (size_t)r_hi * FEAT + col) =
                __floats2half2_rn(acc[nt][2] * di_hi, acc[nt][3] * di_hi);
    }
}

// ---------------------------------------------------------------------------
// Gather: warp per node. result = gelu(dd * (h'[node] + sum h'[s]) + b).
// GELU via hardware tanh.approx (MUFU.TANH); 8-edge unroll with 2-level fp16
// HADD2 tree; exact fp32 tail + self-loop. (Round-10 proven configuration.)
// ---------------------------------------------------------------------------
__device__ __forceinline__ float gelu_fast(float v) {
    // 0.5*v*(1+tanh(0.7978845608*(v + 0.044715*v^3)))
    float t = fmaf(0.044715f * v, v * v, v) * 0.7978845608f;
    float th;
    asm("tanh.approx.f32 %0, %1;" : "=f"(th) : "f"(t));
    return 0.5f * v * (1.0f + th);
}

__device__ __forceinline__ void acc_row(float4& acc, const uint2* __restrict__ hb, int s) {
    uint2 hv = hb[s * 32];
    float2 fa = __half22float2(*reinterpret_cast<const __half2*>(&hv.x));
    float2 fb = __half22float2(*reinterpret_cast<const __half2*>(&hv.y));
    acc.x += fa.x; acc.y += fa.y; acc.z += fb.x; acc.w += fb.y;
}

__device__ __forceinline__ void acc_quad(float4& acc, const uint2 hv[4]) {
    const __half2* p0 = reinterpret_cast<const __half2*>(&hv[0]);
    const __half2* p1 = reinterpret_cast<const __half2*>(&hv[1]);
    const __half2* p2 = reinterpret_cast<const __half2*>(&hv[2]);
    const __half2* p3 = reinterpret_cast<const __half2*>(&hv[3]);
    __half2 xs = __hadd2(__hadd2(p0[0], p1[0]), __hadd2(p2[0], p3[0]));
    __half2 ys = __hadd2(__hadd2(p0[1], p1[1]), __hadd2(p2[1], p3[1]));
    float2 fx = __half22float2(xs);
    float2 fy = __half22float2(ys);
    acc.x += fx.x; acc.y += fx.y; acc.z += fy.x; acc.w += fy.y;
}

__global__ void __launch_bounds__(256)
gather_kernel(int* __restrict__ cnt, const int* __restrict__ list,
              const __half* __restrict__ h,
              const int* __restrict__ src, const int* __restrict__ dst,
              const int* __restrict__ ovf, const int* __restrict__ ovf_cnt,
              const float* __restrict__ b, float* out, int n) {
    int node = blockIdx.x * 8 + (threadIdx.x >> 5);
    if (node >= n) return;
    int lane = threadIdx.x & 31;

    int m = cnt[node];
    float dd = rsqrtf((float)(m + 1));

    const uint2* hb = reinterpret_cast<const uint2*>(h) + lane;  // row stride = 32 uint2

    float4 acc = make_float4(0.f, 0.f, 0.f, 0.f);
    acc_row(acc, hb, node);  // self loop: h'[node], exact fp32 path

    int mb = (m > CAP) ? CAP : m;
    const int* lp = list + (size_t)node * CAP;

    for (int base = 0; base < mb; base += 32) {
        int idx = base + lane;
        int s = (idx < mb) ? lp[idx] : 0;
        int cnum = mb - base; if (cnum > 32) cnum = 32;
        int j = 0;
        for (; j + 7 < cnum; j += 8) {
            uint2 hv[8];
#pragma unroll
            for (int q = 0; q < 8; q++) {
                int sq = __shfl_sync(0xFFFFFFFFu, s, j + q);
                hv[q] = hb[sq * 32];
            }
            acc_quad(acc, hv);
            acc_quad(acc, hv + 4);
        }
        for (; j < cnum; j++) {
            int sj = __shfl_sync(0xFFFFFFFFu, s, j);
            acc_row(acc, hb, sj);  // exact fp32 tail
        }
    }

    if (m > CAP) {  // inline overflow scan (ovf list empty in practice)
        int movf = *ovf_cnt;
        for (int i = 0; i < movf; i++) {
            int e = __ldg(ovf + i);
            if (__ldg(dst + e) == node) acc_row(acc, hb, __ldg(src + e));
        }
    }

    float4 bb = *(reinterpret_cast<const float4*>(b) + lane);
    acc.x = gelu_fast(fmaf(dd, acc.x, bb.x));
    acc.y = gelu_fast(fmaf(dd, acc.y, bb.y));
    acc.z = gelu_fast(fmaf(dd, acc.z, bb.z));
    acc.w = gelu_fast(fmaf(dd, acc.w, bb.w));
    *(reinterpret_cast<float4*>(out + (size_t)node * FEAT) + lane) = acc;

    // Reset cnt for the next replay (zero at module load; restored every run).
    if (lane == 0) cnt[node] = 0;
}

// ---------------------------------------------------------------------------
// Launch: prep -> fill -> gemm (PDL overlap with fill) -> gather
// ---------------------------------------------------------------------------
extern "C" void kernel_launch(void* const* d_in, const int* in_sizes, int n_in,
                              void* d_out, int out_size) {
    const float* x  = (const float*)d_in[0];
    const int*   ei = (const int*)d_in[1];
    const float* W  = (const float*)d_in[2];
    const float* b  = (const float*)d_in[3];
    float* out = (float*)d_out;

    int n = in_sizes[0] / FEAT;
    int E = in_sizes[1] / 2;
    const int* src = ei;
    const int* dst = ei + E;

    __half *h_ptr, *wh_ptr;
    int *cnt_ptr, *list_ptr, *ovf_ptr, *ovfc_ptr;
    cudaGetSymbolAddress((void**)&h_ptr, g_h);
    cudaGetSymbolAddress((void**)&wh_ptr, g_wh);
    cudaGetSymbolAddress((void**)&cnt_ptr, g_cnt);
    cudaGetSymbolAddress((void**)&list_ptr, g_list);
    cudaGetSymbolAddress((void**)&ovf_ptr, g_ovf);
    cudaGetSymbolAddress((void**)&ovfc_ptr, g_ovf_cnt);

    prep_kernel<<<(FEAT * FEAT / 4 + 255) / 256, 256>>>(W, wh_ptr, ovfc_ptr);

    int fill_threads = (E + 3) / 4;
    fill_kernel<<<(fill_threads + 255) / 256, 256>>>(src, dst, cnt_ptr, list_ptr,
                                                     ovf_ptr, ovfc_ptr, E);

    int smem_bytes = (FEAT + BM) * WPADH * (int)sizeof(__half);  // ~68 KB
    cudaFuncSetAttribute(gemm_kernel, cudaFuncAttributeMaxDynamicSharedMemorySize, smem_bytes);

    // gemm with programmatic stream serialization: launches while fill runs,
    // waits (griddepcontrol.wait) only before its cnt-dependent epilogue.
    {
        cudaLaunchConfig_t cfg = {};
        cfg.gridDim = dim3((n + BM - 1) / BM);
        cfg.blockDim = dim3(512);
        cfg.dynamicSmemBytes = (size_t)smem_bytes;
        cfg.stream = 0;
        cudaLaunchAttribute attrs[1];
        attrs[0].id = cudaLaunchAttributeProgrammaticStreamSerialization;
        attrs[0].val.programmaticStreamSerializationAllowed = 1;
        cfg.attrs = attrs;
        cfg.numAttrs = 1;
        cudaLaunchKernelEx(&cfg, gemm_kernel, x, (const __half*)wh_ptr,
                           (const int*)cnt_ptr, h_ptr, n);
    }

    gather_kernel<<<(n + 7) / 8, 256>>>(cnt_ptr, list_ptr, h_ptr,
                                        src, dst, ovf_ptr, ovfc_ptr, b, out, n);
}

// round 17
// speedup vs baseline: 1.0851x; 1.0012x over previous
#include <cuda_runtime.h>
#include <cuda_fp16.h>
#include <cstdint>

#define N_NODES_MAX 50000
#define N_EDGES_MAX 800000
#define FEAT 128
#define BM 128
#define WPADH 136  // padded half row: 272 B = 17*16B -> conflict-free ldmatrix
#define CAP 64     // per-node bucket capacity (deg ~Poisson(16); overflow handled inline)

// Scratch (allocation-free rule: __device__ globals)
__device__ __half g_h[N_NODES_MAX * FEAT];      // h' = (x@W) * dinv[row], fp16
__device__ __half g_wh[FEAT * FEAT];            // fp16 W (converted once per launch)
__device__ int    g_cnt[N_NODES_MAX];           // zero at load; re-zeroed by gather each run
__device__ int    g_list[N_NODES_MAX * CAP];    // bucketed src indices
__device__ int    g_ovf[N_EDGES_MAX];           // overflow edge ids (unused in practice)
__device__ int    g_ovf_cnt;

// ---------------------------------------------------------------------------
// Prep: convert W to fp16 + reset overflow counter
// ---------------------------------------------------------------------------
__global__ void prep_kernel(const float* __restrict__ W, __half* __restrict__ wh,
                            int* ovf_cnt) {
    int i = blockIdx.x * blockDim.x + threadIdx.x;
    if (i == 0) *ovf_cnt = 0;
    if (i < FEAT * FEAT / 4) {
        float4 v = reinterpret_cast<const float4*>(W)[i];
        __half2* d = reinterpret_cast<__half2*>(wh + i * 4);
        d[0] = __floats2half2_rn(v.x, v.y);
        d[1] = __floats2half2_rn(v.z, v.w);
    }
}

// ---------------------------------------------------------------------------
// Fill buckets: 4 edges/thread (782 blocks = single wave). Releases the
// dependent gemm launch immediately via griddepcontrol.launch_dependents —
// gemm's MMA mainloop overlaps fill; gemm waits before reading cnt.
// ---------------------------------------------------------------------------
__global__ void __launch_bounds__(256)
fill_kernel(const int* __restrict__ src, const int* __restrict__ dst,
            int* cnt, int* list, int* ovf, int* ovf_cnt, int E) {
    asm volatile("griddepcontrol.launch_dependents;");
    int i = blockIdx.x * blockDim.x + threadIdx.x;
    int base = i * 4;
    if (base + 3 < E) {
        int4 d4 = *reinterpret_cast<const int4*>(dst + base);
        int4 s4 = *reinterpret_cast<const int4*>(src + base);
        int p0 = atomicAdd(&cnt[d4.x], 1);
        int p1 = atomicAdd(&cnt[d4.y], 1);
        int p2 = atomicAdd(&cnt[d4.z], 1);
        int p3 = atomicAdd(&cnt[d4.w], 1);
        if (p0 < CAP) list[d4.x * CAP + p0] = s4.x; else ovf[atomicAdd(ovf_cnt, 1)] = base;
        if (p1 < CAP) list[d4.y * CAP + p1] = s4.y; else ovf[atomicAdd(ovf_cnt, 1)] = base + 1;
        if (p2 < CAP) list[d4.z * CAP + p2] = s4.z; else ovf[atomicAdd(ovf_cnt, 1)] = base + 2;
        if (p3 < CAP) list[d4.w * CAP + p3] = s4.w; else ovf[atomicAdd(ovf_cnt, 1)] = base + 3;
    } else {
        for (int e = base; e < E; e++) {
            int d = __ldg(dst + e);
            int p = atomicAdd(&cnt[d], 1);
            if (p < CAP) list[d * CAP + p] = __ldg(src + e);
            else         ovf[atomicAdd(ovf_cnt, 1)] = e;
        }
    }
}

// ---------------------------------------------------------------------------
// Tensor-core helpers
// ---------------------------------------------------------------------------
__device__ __forceinline__ uint32_t smem_u32(const void* p) {
    return (uint32_t)__cvta_generic_to_shared(p);
}
__device__ __forceinline__ void ldmatrix_x4(uint32_t& r0, uint32_t& r1,
                                            uint32_t& r2, uint32_t& r3, uint32_t addr) {
    asm volatile("ldmatrix.sync.aligned.m8n8.x4.shared.b16 {%0,%1,%2,%3}, [%4];"
                 : "=r"(r0), "=r"(r1), "=r"(r2), "=r"(r3) : "r"(addr));
}
__device__ __forceinline__ void ldmatrix_x2_trans(uint32_t& r0, uint32_t& r1, uint32_t addr) {
    asm volatile("ldmatrix.sync.aligned.m8n8.x2.trans.shared.b16 {%0,%1}, [%2];"
                 : "=r"(r0), "=r"(r1) : "r"(addr));
}
__device__ __forceinline__ void mma16816(float* c, uint32_t a0, uint32_t a1,
                                         uint32_t a2, uint32_t a3,
                                         uint32_t b0, uint32_t b1) {
    asm volatile(
        "mma.sync.aligned.m16n8k16.row.col.f32.f16.f16.f32 "
        "{%0,%1,%2,%3}, {%4,%5,%6,%7}, {%8,%9}, {%0,%1,%2,%3};"
        : "+f"(c[0]), "+f"(c[1]), "+f"(c[2]), "+f"(c[3])
        : "r"(a0), "r"(a1), "r"(a2), "r"(a3), "r"(b0), "r"(b1));
}

// ---------------------------------------------------------------------------
// GEMM: h' = (x @ W) * rsqrt(cnt[row]+1), fp16 out. Tile 128x128, 512 threads.
// Launched with programmatic stream serialization: the stage + MMA mainloop
// overlaps fill; griddepcontrol.wait before the cnt-dependent epilogue.
// ---------------------------------------------------------------------------
__global__ void __launch_bounds__(512)
gemm_kernel(const float* __restrict__ x, const __half* __restrict__ wh,
            const int* __restrict__ cnt, __half* __restrict__ h, int n) {
    extern __shared__ __half sh[];
    __half* Wh = sh;                    // [128][WPADH]
    __half* Xh = sh + FEAT * WPADH;     // [BM][WPADH]

    int tid = threadIdx.x;
    int r0blk = blockIdx.x * BM;

    // Stage W (already fp16): 2048 uint4
    {
        const uint4* w4 = reinterpret_cast<const uint4*>(wh);
#pragma unroll
        for (int i = 0; i < 4; i++) {
            int idx = i * 512 + tid;
            int r = idx >> 4, c = idx & 15;
            *reinterpret_cast<uint4*>(Wh + r * WPADH + c * 8) = w4[idx];
        }
    }
    // Stage X tile (fp32 -> fp16): 128x32 float4 = 4096
    {
        const float4* x4 = reinterpret_cast<const float4*>(x);
#pragma unroll
        for (int i = 0; i < 8; i++) {
            int idx = i * 512 + tid;
            int r = idx >> 5, c4 = idx & 31;
            int row = r0blk + r;
            float4 v = make_float4(0.f, 0.f, 0.f, 0.f);
            if (row < n) v = x4[(size_t)row * 32 + c4];
            __half2* d = reinterpret_cast<__half2*>(Xh + r * WPADH + c4 * 4);
            d[0] = __floats2half2_rn(v.x, v.y);
            d[1] = __floats2half2_rn(v.z, v.w);
        }
    }
    __syncthreads();

    int w = tid >> 5, lane = tid & 31;
    int wr = w & 7;        // 8 row groups of 16
    int wc = w >> 3;       // 2 col groups of 64

    float acc[8][4];
#pragma unroll
    for (int nt = 0; nt < 8; nt++)
#pragma unroll
        for (int j = 0; j < 4; j++) acc[nt][j] = 0.f;

    int t = lane >> 3, r8 = lane & 7;
    int a_row = wr * 16 + (t & 1) * 8 + r8;
    int a_kof = (t >> 1) * 8;
    uint32_t a_base = smem_u32(Xh + a_row * WPADH + a_kof);
    int bt = (lane >> 3) & 1;
    uint32_t b_base = smem_u32(Wh + (bt * 8 + r8) * WPADH + wc * 64);

#pragma unroll
    for (int kk = 0; kk < 8; kk++) {
        uint32_t a0, a1, a2, a3;
        ldmatrix_x4(a0, a1, a2, a3, a_base + kk * 16 * sizeof(__half));
        uint32_t brow = b_base + kk * 16 * WPADH * sizeof(__half);
#pragma unroll
        for (int nt = 0; nt < 8; nt++) {
            uint32_t b0, b1;
            ldmatrix_x2_trans(b0, b1, brow + nt * 8 * sizeof(__half));
            mma16816(acc[nt], a0, a1, a2, a3, b0, b1);
        }
    }

    // Wait for fill (primary) to complete before consuming cnt.
    asm volatile("griddepcontrol.wait;" ::: "memory");

    int group = lane >> 2, tg = lane & 3;
    int r_lo = r0blk + wr * 16 + group;
    int r_hi = r_lo + 8;
    float di_lo = (r_lo < n) ? rsqrtf((float)(__ldg(cnt + r_lo) + 1)) : 0.f;
    float di_hi = (r_hi < n) ? rsqrtf((float)(__ldg(cnt + r_hi) + 1)) : 0.f;

#pragma unroll
    for (int nt = 0; nt < 8; nt++) {
        int col = wc * 64 + nt * 8 + tg * 2;
        if (r_lo < n)
            *reinterpret_cast<__half2*>(h + (size_t)r_lo * FEAT + col) =
                __floats2half2_rn(acc[nt][0] * di_lo, acc[nt][1] * di_lo);
        if (r_hi < n)
            *reinterpret_cast<__half2*>(h + (size_t)r_hi * FEAT + col) =
                __floats2half2_rn(acc[nt][2] * di_hi, acc[nt][3] * di_hi);
    }
}

// ---------------------------------------------------------------------------
// Gather: warp per node. result = gelu(dd * (h'[node] + sum h'[s]) + b).
// GELU via hardware tanh.approx; 8-edge unroll with a 3-level fp16 HADD2 tree
// (one convert+add per 8 edges per half2 position); exact fp32 tail+self-loop.
// ---------------------------------------------------------------------------
__device__ __forceinline__ float gelu_fast(float v) {
    // 0.5*v*(1+tanh(0.7978845608*(v + 0.044715*v^3)))
    float t = fmaf(0.044715f * v, v * v, v) * 0.7978845608f;
    float th;
    asm("tanh.approx.f32 %0, %1;" : "=f"(th) : "f"(t));
    return 0.5f * v * (1.0f + th);
}

__device__ __forceinline__ void acc_row(float4& acc, const uint2* __restrict__ hb, int s) {
    uint2 hv = hb[s * 32];
    float2 fa = __half22float2(*reinterpret_cast<const __half2*>(&hv.x));
    float2 fb = __half22float2(*reinterpret_cast<const __half2*>(&hv.y));
    acc.x += fa.x; acc.y += fa.y; acc.z += fb.x; acc.w += fb.y;
}

// 3-level fp16 tree over 8 rows: 14 HADD2 + 2 half2->float2 + 4 FADD.
__device__ __forceinline__ void acc_oct(float4& acc, const uint2 hv[8]) {
    __half2 x0 = __hadd2(*reinterpret_cast<const __half2*>(&hv[0].x),
                         *reinterpret_cast<const __half2*>(&hv[1].x));
    __half2 x1 = __hadd2(*reinterpret_cast<const __half2*>(&hv[2].x),
                         *reinterpret_cast<const __half2*>(&hv[3].x));
    __half2 x2 = __hadd2(*reinterpret_cast<const __half2*>(&hv[4].x),
                         *reinterpret_cast<const __half2*>(&hv[5].x));
    __half2 x3 = __hadd2(*reinterpret_cast<const __half2*>(&hv[6].x),
                         *reinterpret_cast<const __half2*>(&hv[7].x));
    __half2 xs = __hadd2(__hadd2(x0, x1), __hadd2(x2, x3));

    __half2 y0 = __hadd2(*reinterpret_cast<const __half2*>(&hv[0].y),
                         *reinterpret_cast<const __half2*>(&hv[1].y));
    __half2 y1 = __hadd2(*reinterpret_cast<const __half2*>(&hv[2].y),
                         *reinterpret_cast<const __half2*>(&hv[3].y));
    __half2 y2 = __hadd2(*reinterpret_cast<const __half2*>(&hv[4].y),
                         *reinterpret_cast<const __half2*>(&hv[5].y));
    __half2 y3 = __hadd2(*reinterpret_cast<const __half2*>(&hv[6].y),
                         *reinterpret_cast<const __half2*>(&hv[7].y));
    __half2 ys = __hadd2(__hadd2(y0, y1), __hadd2(y2, y3));

    float2 fx = __half22float2(xs);
    float2 fy = __half22float2(ys);
    acc.x += fx.x; acc.y += fx.y; acc.z += fy.x; acc.w += fy.y;
}

__global__ void __launch_bounds__(256)
gather_kernel(int* __restrict__ cnt, const int* __restrict__ list,
              const __half* __restrict__ h,
              const int* __restrict__ src, const int* __restrict__ dst,
              const int* __restrict__ ovf, const int* __restrict__ ovf_cnt,
              const float* __restrict__ b, float* out, int n) {
    int node = blockIdx.x * 8 + (threadIdx.x >> 5);
    if (node >= n) return;
    int lane = threadIdx.x & 31;

    int m = cnt[node];
    float dd = rsqrtf((float)(m + 1));

    const uint2* hb = reinterpret_cast<const uint2*>(h) + lane;  // row stride = 32 uint2

    float4 acc = make_float4(0.f, 0.f, 0.f, 0.f);
    acc_row(acc, hb, node);  // self loop: h'[node], exact fp32 path

    int mb = (m > CAP) ? CAP : m;
    const int* lp = list + (size_t)node * CAP;

    for (int base = 0; base < mb; base += 32) {
        int idx = base + lane;
        int s = (idx < mb) ? lp[idx] : 0;
        int cnum = mb - base; if (cnum > 32) cnum = 32;
        int j = 0;
        for (; j + 7 < cnum; j += 8) {
            uint2 hv[8];
#pragma unroll
            for (int q = 0; q < 8; q++) {
                int sq = __shfl_sync(0xFFFFFFFFu, s, j + q);
                hv[q] = hb[sq * 32];
            }
            acc_oct(acc, hv);
        }
        for (; j < cnum; j++) {
            int sj = __shfl_sync(0xFFFFFFFFu, s, j);
            acc_row(acc, hb, sj);  // exact fp32 tail
        }
    }

    if (m > CAP) {  // inline overflow scan (ovf list empty in practice)
        int movf = *ovf_cnt;
        for (int i = 0; i < movf; i++) {
            int e = __ldg(ovf + i);
            if (__ldg(dst + e) == node) acc_row(acc, hb, __ldg(src + e));
        }
    }

    float4 bb = *(reinterpret_cast<const float4*>(b) + lane);
    acc.x = gelu_fast(fmaf(dd, acc.x, bb.x));
    acc.y = gelu_fast(fmaf(dd, acc.y, bb.y));
    acc.z = gelu_fast(fmaf(dd, acc.z, bb.z));
    acc.w = gelu_fast(fmaf(dd, acc.w, bb.w));
    *(reinterpret_cast<float4*>(out + (size_t)node * FEAT) + lane) = acc;

    // Reset cnt for the next replay (zero at module load; restored every run).
    if (lane == 0) cnt[node] = 0;
}

// ---------------------------------------------------------------------------
// Launch: prep -> fill -> gemm (PDL overlap with fill) -> gather
// ---------------------------------------------------------------------------
extern "C" void kernel_launch(void* const* d_in, const int* in_sizes, int n_in,
                              void* d_out, int out_size) {
    const float* x  = (const float*)d_in[0];
    const int*   ei = (const int*)d_in[1];
    const float* W  = (const float*)d_in[2];
    const float* b  = (const float*)d_in[3];
    float* out = (float*)d_out;

    int n = in_sizes[0] / FEAT;
    int E = in_sizes[1] / 2;
    const int* src = ei;
    const int* dst = ei + E;

    __half *h_ptr, *wh_ptr;
    int *cnt_ptr, *list_ptr, *ovf_ptr, *ovfc_ptr;
    cudaGetSymbolAddress((void**)&h_ptr, g_h);
    cudaGetSymbolAddress((void**)&wh_ptr, g_wh);
    cudaGetSymbolAddress((void**)&cnt_ptr, g_cnt);
    cudaGetSymbolAddress((void**)&list_ptr, g_list);
    cudaGetSymbolAddress((void**)&ovf_ptr, g_ovf);
    cudaGetSymbolAddress((void**)&ovfc_ptr, g_ovf_cnt);

    prep_kernel<<<(FEAT * FEAT / 4 + 255) / 256, 256>>>(W, wh_ptr, ovfc_ptr);

    int fill_threads = (E + 3) / 4;
    fill_kernel<<<(fill_threads + 255) / 256, 256>>>(src, dst, cnt_ptr, list_ptr,
                                                     ovf_ptr, ovfc_ptr, E);

    int smem_bytes = (FEAT + BM) * WPADH * (int)sizeof(__half);  // ~68 KB
    cudaFuncSetAttribute(gemm_kernel, cudaFuncAttributeMaxDynamicSharedMemorySize, smem_bytes);

    // gemm with programmatic stream serialization: launches while fill runs,
    // waits (griddepcontrol.wait) only before its cnt-dependent epilogue.
    {
        cudaLaunchConfig_t cfg = {};
        cfg.gridDim = dim3((n + BM - 1) / BM);
        cfg.blockDim = dim3(512);
        cfg.dynamicSmemBytes = (size_t)smem_bytes;
        cfg.stream = 0;
        cudaLaunchAttribute attrs[1];
        attrs[0].id = cudaLaunchAttributeProgrammaticStreamSerialization;
        attrs[0].val.programmaticStreamSerializationAllowed = 1;
        cfg.attrs = attrs;
        cfg.numAttrs = 1;
        cudaLaunchKernelEx(&cfg, gemm_kernel, x, (const __half*)wh_ptr,
                           (const int*)cnt_ptr, h_ptr, n);
    }

    gather_kernel<<<(n + 7) / 8, 256>>>(cnt_ptr, list_ptr, h_ptr,
                                        src, dst, ovf_ptr, ovfc_ptr, b, out, n);
}